// round 3
// baseline (speedup 1.0000x reference)
#include <cuda_runtime.h>
#include <math.h>

// Problem constants
#define G_    64
#define NPG   256
#define EPG   4096
#define NN    (G_*NPG)     // 16384 nodes
#define EE    (G_*EPG)     // 262144 edges
#define IN_C  256
#define OHC_  8
#define HH    4
#define CC    64
#define HC    256          // H*C
#define KDIM  (IN_C+OHC_)  // 264

// Scratch (device globals; no allocation allowed)
__device__ int   g_deg[NN];
__device__ int   g_off[NN];
__device__ int   g_cur[NN];
__device__ int   g_esrc[EE];
__device__ float g_ohfeat[NN*OHC_];
__device__ float g_xp[NN*HC];
__device__ __align__(16) float g_al[NN*HH];
__device__ float g_ar[NN*HH];

// ---------------------------------------------------------------------------
// 1. Zero degree histogram
__global__ void k_zero() {
    int i = blockIdx.x * 256 + threadIdx.x;
    if (i < NN) g_deg[i] = 0;
}

// 2. Histogram of destination degrees (adjs is int32: [G,2,EPG])
__global__ void k_hist(const int* __restrict__ adjs) {
    int e  = blockIdx.x * 256 + threadIdx.x;
    if (e >= EE) return;
    int g  = e >> 12;          // /EPG
    int le = e & (EPG - 1);
    int dst = adjs[g * 2 * EPG + EPG + le];
    atomicAdd(&g_deg[g * NPG + dst], 1);
}

// 3. Per-graph exclusive scan (each graph owns exactly EPG edge slots)
__global__ void k_scan() {
    __shared__ int s[NPG];
    int g = blockIdx.x, t = threadIdx.x;
    int d = g_deg[g * NPG + t];
    s[t] = d;
    for (int o = 1; o < NPG; o <<= 1) {
        __syncthreads();
        int v = (t >= o) ? s[t - o] : 0;
        __syncthreads();
        s[t] += v;
    }
    __syncthreads();
    int off = g * EPG + s[t] - d;   // exclusive prefix + graph base
    g_off[g * NPG + t] = off;
    g_cur[g * NPG + t] = off;
}

// 4. Scatter source ids into CSR slots
__global__ void k_scatter(const int* __restrict__ adjs) {
    int e  = blockIdx.x * 256 + threadIdx.x;
    if (e >= EE) return;
    int g  = e >> 12;
    int le = e & (EPG - 1);
    int base = g * 2 * EPG;
    int src = adjs[base + le];
    int dst = adjs[base + EPG + le];
    int pos = atomicAdd(&g_cur[g * NPG + dst], 1);
    g_esrc[pos] = g * NPG + src;
}

// ---------------------------------------------------------------------------
// 5. Per-node: sort row, conv1d(1->8)+relu, conv1d(8->16)+relu, mean, fc -> oh_feat
__global__ void __launch_bounds__(256) k_conv(
    const float* __restrict__ oh,
    const float* __restrict__ w1, const float* __restrict__ b1,
    const float* __restrict__ w2, const float* __restrict__ b2,
    const float* __restrict__ fcw, const float* __restrict__ fcb)
{
    __shared__ float s[256];
    __shared__ float z1[8][258];
    __shared__ float sw2[16 * 24];
    __shared__ float sp[8 * 16];
    __shared__ float smean[16];

    int n = blockIdx.x, t = threadIdx.x;

    for (int i = t; i < 384; i += 256) sw2[i] = w2[i];

    // --- bitonic sort of the 256-element row (ascending) ---
    s[t] = oh[(size_t)n * 256 + t];
    for (int k = 2; k <= 256; k <<= 1) {
        for (int j = k >> 1; j > 0; j >>= 1) {
            __syncthreads();
            int p = t ^ j;
            float a = s[t], b = s[p];
            bool up = ((t & k) == 0);
            float keep;
            if (t < p) keep = up ? fminf(a, b) : fmaxf(a, b);
            else       keep = up ? fmaxf(a, b) : fminf(a, b);
            __syncthreads();
            s[t] = keep;
        }
    }
    __syncthreads();

    // --- conv1: 1 -> 8 channels, k=3, zero 'same' padding, relu ---
    float left  = (t > 0)   ? s[t - 1] : 0.f;
    float mid   = s[t];
    float right = (t < 255) ? s[t + 1] : 0.f;
#pragma unroll
    for (int oc = 0; oc < 8; oc++) {
        float v = b1[oc] + w1[oc*3 + 0]*left + w1[oc*3 + 1]*mid + w1[oc*3 + 2]*right;
        z1[oc][t + 1] = fmaxf(v, 0.f);
    }
    if (t < 8)       z1[t][0]       = 0.f;
    else if (t < 16) z1[t - 8][257] = 0.f;
    __syncthreads();

    // --- conv2: 8 -> 16 channels, relu, accumulate means ---
    float tap[24];
#pragma unroll
    for (int ic = 0; ic < 8; ic++) {
        tap[ic*3 + 0] = z1[ic][t];
        tap[ic*3 + 1] = z1[ic][t + 1];
        tap[ic*3 + 2] = z1[ic][t + 2];
    }
    float acc[16];
#pragma unroll
    for (int oc = 0; oc < 16; oc++) {
        float v = b2[oc];
#pragma unroll
        for (int j = 0; j < 24; j++) v = fmaf(sw2[oc*24 + j], tap[j], v);
        acc[oc] = fmaxf(v, 0.f);
    }

    // block reduction over L for the 16 channels
    int lane = t & 31, wid = t >> 5;
#pragma unroll
    for (int oc = 0; oc < 16; oc++) {
        float v = acc[oc];
#pragma unroll
        for (int o = 16; o > 0; o >>= 1) v += __shfl_down_sync(0xffffffffu, v, o);
        if (lane == 0) sp[wid * 16 + oc] = v;
    }
    __syncthreads();
    if (t < 16) {
        float m = 0.f;
#pragma unroll
        for (int w = 0; w < 8; w++) m += sp[w * 16 + t];
        smean[t] = m * (1.0f / 256.0f);
    }
    __syncthreads();
    if (t < 8) {
        float v = fcb[t];
#pragma unroll
        for (int ic = 0; ic < 16; ic++) v = fmaf(smean[ic], fcw[ic * 8 + t], v);
        g_ohfeat[n * 8 + t] = v;
    }
}

// ---------------------------------------------------------------------------
// 6. xp = [x | oh_feat] @ lin_w   ([16384,264] x [264,256])
__global__ void __launch_bounds__(256) k_gemm(
    const float* __restrict__ x, const float* __restrict__ lw)
{
    __shared__ float a[16][8];
    int t  = threadIdx.x;
    int n0 = blockIdx.x * 16;
    float acc[16];
#pragma unroll
    for (int r = 0; r < 16; r++) acc[r] = 0.f;

    for (int k0 = 0; k0 < KDIM; k0 += 8) {
        __syncthreads();
        if (t < 128) {
            int r = t >> 3, kk = t & 7;
            int k = k0 + kk;
            float v = (k < 256) ? x[(size_t)(n0 + r) * 256 + k]
                                : g_ohfeat[(n0 + r) * 8 + (k - 256)];
            a[r][kk] = v;
        }
        __syncthreads();
#pragma unroll
        for (int kk = 0; kk < 8; kk++) {
            float w = lw[(size_t)(k0 + kk) * 256 + t];
#pragma unroll
            for (int r = 0; r < 16; r++) acc[r] = fmaf(a[r][kk], w, acc[r]);
        }
    }
#pragma unroll
    for (int r = 0; r < 16; r++) g_xp[(size_t)(n0 + r) * 256 + t] = acc[r];
}

// ---------------------------------------------------------------------------
// 7. alpha_l / alpha_r : per-head dot of xp with att vectors
__global__ void __launch_bounds__(256) k_alpha(
    const float* __restrict__ attl, const float* __restrict__ attr)
{
    __shared__ float spl[8], spr[8];
    int n = blockIdx.x, t = threadIdx.x;
    float v = g_xp[(size_t)n * 256 + t];
    float p = v * attl[t];
    float q = v * attr[t];
#pragma unroll
    for (int o = 16; o > 0; o >>= 1) {
        p += __shfl_down_sync(0xffffffffu, p, o);
        q += __shfl_down_sync(0xffffffffu, q, o);
    }
    int wid = t >> 5;
    if ((t & 31) == 0) { spl[wid] = p; spr[wid] = q; }
    __syncthreads();
    if (t < 4) {
        g_al[n * 4 + t] = spl[2*t] + spl[2*t + 1];
        g_ar[n * 4 + t] = spr[2*t] + spr[2*t + 1];
    }
}

// ---------------------------------------------------------------------------
// 8. Combined gather-side aggregation: attention softmax-weighted sum of xp,
//    and onehot row scatter-add (gather form) + residual.
#define CHUNK 128
__global__ void __launch_bounds__(256) k_agg(
    const float* __restrict__ oh,
    const float* __restrict__ bias,
    float* __restrict__ out)
{
    __shared__ int   ssrc[CHUNK];
    __shared__ float sal[CHUNK * 4];

    int n = blockIdx.x, t = threadIdx.x;
    int g = n >> 8;
    int h = t >> 6;
    float arh = g_ar[n * 4 + h];
    const float* ohg = oh + (size_t)g * (NPG * NPG);

    float accx = 0.f, den = 0.f;
    float acco = ohg[(size_t)(n & 255) * 256 + t];   // residual term

    int beg = g_off[n];
    int cnt = g_deg[n];

    for (int c0 = 0; c0 < cnt; c0 += CHUNK) {
        int m = min(CHUNK, cnt - c0);
        __syncthreads();
        if (t < m) {
            int s = g_esrc[beg + c0 + t];
            ssrc[t] = s;
            float4 v = *(const float4*)&g_al[s * 4];
            sal[t*4 + 0] = v.x; sal[t*4 + 1] = v.y;
            sal[t*4 + 2] = v.z; sal[t*4 + 3] = v.w;
        }
        __syncthreads();
#pragma unroll 4
        for (int i = 0; i < m; i++) {
            int s = ssrc[i];
            float l = sal[i*4 + h] + arh;
            l = (l > 0.f) ? l : 0.2f * l;              // leaky_relu
            float w = __expf(l);
            den  += w;
            accx  = fmaf(w, g_xp[(size_t)s * 256 + t], accx);
            acco += ohg[(size_t)(s & 255) * 256 + t];
        }
    }

    out[(size_t)n * 256 + t] = accx / (den + 1e-16f) + bias[t];
    out[(size_t)NN * 256 + (size_t)n * 256 + t] = acco;
}

// ---------------------------------------------------------------------------
extern "C" void kernel_launch(void* const* d_in, const int* in_sizes, int n_in,
                              void* d_out, int out_size)
{
    const float* x     = (const float*)d_in[0];
    const float* oh    = (const float*)d_in[1];
    const int*   adjs  = (const int*)d_in[2];
    const float* lin_w = (const float*)d_in[3];
    const float* att_l = (const float*)d_in[4];
    const float* att_r = (const float*)d_in[5];
    const float* bias  = (const float*)d_in[6];
    const float* c1w   = (const float*)d_in[7];
    const float* c1b   = (const float*)d_in[8];
    const float* c2w   = (const float*)d_in[9];
    const float* c2b   = (const float*)d_in[10];
    const float* fcw   = (const float*)d_in[11];
    const float* fcb   = (const float*)d_in[12];
    float* out = (float*)d_out;

    // CSR build
    k_zero<<<NN / 256, 256>>>();
    k_hist<<<EE / 256, 256>>>(adjs);
    k_scan<<<G_, 256>>>();
    k_scatter<<<EE / 256, 256>>>(adjs);

    // node features
    k_conv<<<NN, 256>>>(oh, c1w, c1b, c2w, c2b, fcw, fcb);
    k_gemm<<<NN / 16, 256>>>(x, lin_w);
    k_alpha<<<NN, 256>>>(att_l, att_r);

    // aggregation + outputs
    k_agg<<<NN, 256>>>(oh, bias, out);
}

// round 4
// speedup vs baseline: 1.2593x; 1.2593x over previous
#include <cuda_runtime.h>
#include <math.h>

// Problem constants
#define G_    64
#define NPG   256
#define EPG   4096
#define NN    (G_*NPG)     // 16384 nodes
#define EE    (G_*EPG)     // 262144 edges
#define IN_C  256
#define OHC_  8
#define HH    4
#define CC    64
#define HC    256          // H*C
#define KDIM  (IN_C+OHC_)  // 264

// Scratch (device globals; no allocation allowed)
__device__ int   g_deg[NN];
__device__ int   g_off[NN];
__device__ int   g_cur[NN];
__device__ int   g_esrc[EE];
__device__ float g_ohfeat[NN*OHC_];
__device__ float g_xp[NN*HC];
__device__ __align__(16) float g_al[NN*HH];
__device__ float g_ar[NN*HH];

// ---------------------------------------------------------------------------
// 1. Fused CSR prefix: per-graph smem histogram + scan (one block per graph)
__global__ void __launch_bounds__(256) k_csr(const int* __restrict__ adjs) {
    __shared__ int sdeg[NPG];
    __shared__ int s[NPG];
    int g = blockIdx.x, t = threadIdx.x;
    sdeg[t] = 0;
    __syncthreads();
    const int* dsts = adjs + g * 2 * EPG + EPG;
#pragma unroll 4
    for (int e = t; e < EPG; e += 256)
        atomicAdd(&sdeg[dsts[e]], 1);
    __syncthreads();
    int d = sdeg[t];
    s[t] = d;
    for (int o = 1; o < NPG; o <<= 1) {
        __syncthreads();
        int v = (t >= o) ? s[t - o] : 0;
        __syncthreads();
        s[t] += v;
    }
    __syncthreads();
    int off = g * EPG + s[t] - d;   // exclusive prefix + graph base
    g_deg[g * NPG + t] = d;
    g_off[g * NPG + t] = off;
    g_cur[g * NPG + t] = off;
}

// 2. Scatter source ids into CSR slots
__global__ void k_scatter(const int* __restrict__ adjs) {
    int e  = blockIdx.x * 256 + threadIdx.x;
    if (e >= EE) return;
    int g  = e >> 12;
    int le = e & (EPG - 1);
    int base = g * 2 * EPG;
    int src = adjs[base + le];
    int dst = adjs[base + EPG + le];
    int pos = atomicAdd(&g_cur[g * NPG + dst], 1);
    g_esrc[pos] = g * NPG + src;
}

// ---------------------------------------------------------------------------
// 3. Per-node: sort row (register bitonic + shfl), conv1(1->8), conv2(8->16),
//    mean, fc -> oh_feat
__global__ void __launch_bounds__(256) k_conv(
    const float* __restrict__ oh,
    const float* __restrict__ w1, const float* __restrict__ b1,
    const float* __restrict__ w2, const float* __restrict__ b2,
    const float* __restrict__ fcw, const float* __restrict__ fcb)
{
    __shared__ float s[256];
    __shared__ float z1[8][258];
    __shared__ float sw2[16 * 24];
    __shared__ float sp[8 * 16];
    __shared__ float smean[16];

    int n = blockIdx.x, t = threadIdx.x;

    for (int i = t; i < 384; i += 256) sw2[i] = w2[i];

    // --- bitonic sort, value in register; shfl for j<32, smem for j>=32 ---
    float v = oh[(size_t)n * 256 + t];
#pragma unroll
    for (int k = 2; k <= 256; k <<= 1) {
        for (int j = k >> 1; j > 0; j >>= 1) {
            float o;
            if (j >= 32) {
                __syncthreads();
                s[t] = v;
                __syncthreads();
                o = s[t ^ j];
            } else {
                o = __shfl_xor_sync(0xffffffffu, v, j);
            }
            bool up    = ((t & k) == 0);
            bool lower = ((t & j) == 0);
            v = (lower == up) ? fminf(v, o) : fmaxf(v, o);
        }
    }
    __syncthreads();
    s[t] = v;
    __syncthreads();

    // --- conv1: 1 -> 8 channels, k=3, zero 'same' padding, relu ---
    float left  = (t > 0)   ? s[t - 1] : 0.f;
    float mid   = s[t];
    float right = (t < 255) ? s[t + 1] : 0.f;
#pragma unroll
    for (int oc = 0; oc < 8; oc++) {
        float z = b1[oc] + w1[oc*3 + 0]*left + w1[oc*3 + 1]*mid + w1[oc*3 + 2]*right;
        z1[oc][t + 1] = fmaxf(z, 0.f);
    }
    if (t < 8)       z1[t][0]       = 0.f;
    else if (t < 16) z1[t - 8][257] = 0.f;
    __syncthreads();

    // --- conv2: 8 -> 16 channels, relu ---
    float tap[24];
#pragma unroll
    for (int ic = 0; ic < 8; ic++) {
        tap[ic*3 + 0] = z1[ic][t];
        tap[ic*3 + 1] = z1[ic][t + 1];
        tap[ic*3 + 2] = z1[ic][t + 2];
    }
    float acc[16];
#pragma unroll
    for (int oc = 0; oc < 16; oc++) {
        float z = b2[oc];
#pragma unroll
        for (int j = 0; j < 24; j++) z = fmaf(sw2[oc*24 + j], tap[j], z);
        acc[oc] = fmaxf(z, 0.f);
    }

    // block reduction over L for the 16 channels
    int lane = t & 31, wid = t >> 5;
#pragma unroll
    for (int oc = 0; oc < 16; oc++) {
        float z = acc[oc];
#pragma unroll
        for (int o = 16; o > 0; o >>= 1) z += __shfl_down_sync(0xffffffffu, z, o);
        if (lane == 0) sp[wid * 16 + oc] = z;
    }
    __syncthreads();
    if (t < 16) {
        float m = 0.f;
#pragma unroll
        for (int w = 0; w < 8; w++) m += sp[w * 16 + t];
        smean[t] = m * (1.0f / 256.0f);
    }
    __syncthreads();
    if (t < 8) {
        float z = fcb[t];
#pragma unroll
        for (int ic = 0; ic < 16; ic++) z = fmaf(smean[ic], fcw[ic * 8 + t], z);
        g_ohfeat[n * 8 + t] = z;
    }
}

// ---------------------------------------------------------------------------
// 4. xp = [x | oh_feat] @ lin_w  ([16384,264]x[264,256]) + fused alpha_l/r.
//    Block: 32 rows x 256 cols. Thread: 8 rows x 4 cols register tile.
__global__ void __launch_bounds__(256) k_gemm(
    const float* __restrict__ x, const float* __restrict__ lw,
    const float* __restrict__ attl, const float* __restrict__ attr)
{
    __shared__ float sa[8][32];      // [kk][row]
    __shared__ float sw[8][256];     // [kk][col]
    __shared__ float sattl[256], sattr[256];
    __shared__ float sredl[8][2][8]; // [warp][lane16][row-in-group]
    __shared__ float sredr[8][2][8];

    int t  = threadIdx.x;
    int n0 = blockIdx.x * 32;
    int cg = t & 63;            // col group -> cols cg*4 .. cg*4+3
    int rg = t >> 6;            // row group -> rows rg*8 .. rg*8+7
    int c0 = cg * 4;

    sattl[t] = attl[t];
    sattr[t] = attr[t];

    float acc[8][4];
#pragma unroll
    for (int r = 0; r < 8; r++)
#pragma unroll
        for (int c = 0; c < 4; c++) acc[r][c] = 0.f;

    int arow = t & 31, akk = t >> 5;

    for (int k0 = 0; k0 < KDIM; k0 += 8) {
        // stage gmem loads into registers
        int k = k0 + akk;
        float a_ld = (k < 256) ? x[(size_t)(n0 + arow) * 256 + k]
                               : g_ohfeat[(n0 + arow) * 8 + (k - 256)];
        float4 w_ld0, w_ld1;
        {
            int q0 = t, q1 = t + 256;
            w_ld0 = *(const float4*)&lw[(size_t)(k0 + (q0 >> 6)) * 256 + (q0 & 63) * 4];
            w_ld1 = *(const float4*)&lw[(size_t)(k0 + (q1 >> 6)) * 256 + (q1 & 63) * 4];
        }
        __syncthreads();
        sa[akk][arow] = a_ld;
        *(float4*)&sw[(t >> 6)][(t & 63) * 4]          = w_ld0;
        *(float4*)&sw[((t + 256) >> 6)][(t & 63) * 4]  = w_ld1;
        __syncthreads();
#pragma unroll
        for (int kk = 0; kk < 8; kk++) {
            float4 w4 = *(const float4*)&sw[kk][c0];
            float4 a0 = *(const float4*)&sa[kk][rg * 8];
            float4 a1 = *(const float4*)&sa[kk][rg * 8 + 4];
            float av[8] = {a0.x, a0.y, a0.z, a0.w, a1.x, a1.y, a1.z, a1.w};
            float wv[4] = {w4.x, w4.y, w4.z, w4.w};
#pragma unroll
            for (int r = 0; r < 8; r++)
#pragma unroll
                for (int c = 0; c < 4; c++)
                    acc[r][c] = fmaf(av[r], wv[c], acc[r][c]);
        }
    }

    // store xp
#pragma unroll
    for (int r = 0; r < 8; r++) {
        float4 o4 = make_float4(acc[r][0], acc[r][1], acc[r][2], acc[r][3]);
        *(float4*)&g_xp[(size_t)(n0 + rg * 8 + r) * 256 + c0] = o4;
    }

    // fused alpha: per-row, per-head dot. Each thread's 4 cols lie in one head.
    float pl[8], pr[8];
#pragma unroll
    for (int r = 0; r < 8; r++) {
        float l = 0.f, rr = 0.f;
#pragma unroll
        for (int c = 0; c < 4; c++) {
            l  = fmaf(acc[r][c], sattl[c0 + c], l);
            rr = fmaf(acc[r][c], sattr[c0 + c], rr);
        }
        pl[r] = l; pr[r] = rr;
    }
    // reduce within 16-lane segments (one head spans 16 col-groups = 16 lanes)
#pragma unroll
    for (int o = 8; o > 0; o >>= 1) {
#pragma unroll
        for (int r = 0; r < 8; r++) {
            pl[r] += __shfl_down_sync(0xffffffffu, pl[r], o, 16);
            pr[r] += __shfl_down_sync(0xffffffffu, pr[r], o, 16);
        }
    }
    int lane = t & 31, w = t >> 5;
    if (lane == 0 || lane == 16) {
        int half = lane >> 4;
#pragma unroll
        for (int r = 0; r < 8; r++) {
            sredl[w][half][r] = pl[r];
            sredr[w][half][r] = pr[r];
        }
    }
    __syncthreads();
    if (t < 32) {
        int rgx = t >> 3, rr = t & 7;
        int n = n0 + t;
        // warp 2*rgx holds heads 0,1 ; warp 2*rgx+1 holds heads 2,3
        g_al[n * 4 + 0] = sredl[2 * rgx][0][rr];
        g_al[n * 4 + 1] = sredl[2 * rgx][1][rr];
        g_al[n * 4 + 2] = sredl[2 * rgx + 1][0][rr];
        g_al[n * 4 + 3] = sredl[2 * rgx + 1][1][rr];
        g_ar[n * 4 + 0] = sredr[2 * rgx][0][rr];
        g_ar[n * 4 + 1] = sredr[2 * rgx][1][rr];
        g_ar[n * 4 + 2] = sredr[2 * rgx + 1][0][rr];
        g_ar[n * 4 + 3] = sredr[2 * rgx + 1][1][rr];
    }
}

// ---------------------------------------------------------------------------
// 5. Combined gather-side aggregation: attention softmax-weighted sum of xp,
//    and onehot row scatter-add (gather form) + residual.
#define CHUNK 128
__global__ void __launch_bounds__(256) k_agg(
    const float* __restrict__ oh,
    const float* __restrict__ bias,
    float* __restrict__ out)
{
    __shared__ int   ssrc[CHUNK];
    __shared__ float sal[CHUNK * 4];

    int n = blockIdx.x, t = threadIdx.x;
    int g = n >> 8;
    int h = t >> 6;
    float arh = g_ar[n * 4 + h];
    const float* ohg = oh + (size_t)g * (NPG * NPG);

    float accx = 0.f, den = 0.f;
    float acco = ohg[(size_t)(n & 255) * 256 + t];   // residual term

    int beg = g_off[n];
    int cnt = g_deg[n];

    for (int c0 = 0; c0 < cnt; c0 += CHUNK) {
        int m = min(CHUNK, cnt - c0);
        __syncthreads();
        if (t < m) {
            int s = g_esrc[beg + c0 + t];
            ssrc[t] = s;
            float4 v = *(const float4*)&g_al[s * 4];
            sal[t*4 + 0] = v.x; sal[t*4 + 1] = v.y;
            sal[t*4 + 2] = v.z; sal[t*4 + 3] = v.w;
        }
        __syncthreads();
#pragma unroll 4
        for (int i = 0; i < m; i++) {
            int s = ssrc[i];
            float l = sal[i*4 + h] + arh;
            l = (l > 0.f) ? l : 0.2f * l;              // leaky_relu
            float w = __expf(l);
            den  += w;
            accx  = fmaf(w, g_xp[(size_t)s * 256 + t], accx);
            acco += ohg[(size_t)(s & 255) * 256 + t];
        }
    }

    out[(size_t)n * 256 + t] = accx / (den + 1e-16f) + bias[t];
    out[(size_t)NN * 256 + (size_t)n * 256 + t] = acco;
}

// ---------------------------------------------------------------------------
extern "C" void kernel_launch(void* const* d_in, const int* in_sizes, int n_in,
                              void* d_out, int out_size)
{
    const float* x     = (const float*)d_in[0];
    const float* oh    = (const float*)d_in[1];
    const int*   adjs  = (const int*)d_in[2];
    const float* lin_w = (const float*)d_in[3];
    const float* att_l = (const float*)d_in[4];
    const float* att_r = (const float*)d_in[5];
    const float* bias  = (const float*)d_in[6];
    const float* c1w   = (const float*)d_in[7];
    const float* c1b   = (const float*)d_in[8];
    const float* c2w   = (const float*)d_in[9];
    const float* c2b   = (const float*)d_in[10];
    const float* fcw   = (const float*)d_in[11];
    const float* fcb   = (const float*)d_in[12];
    float* out = (float*)d_out;

    // CSR build
    k_csr<<<G_, 256>>>(adjs);
    k_scatter<<<EE / 256, 256>>>(adjs);

    // node features
    k_conv<<<NN, 256>>>(oh, c1w, c1b, c2w, c2b, fcw, fcb);
    k_gemm<<<NN / 32, 256>>>(x, lin_w, att_l, att_r);

    // aggregation + outputs
    k_agg<<<NN, 256>>>(oh, bias, out);
}